// round 13
// baseline (speedup 1.0000x reference)
#include <cuda_runtime.h>
#include <cuda_bf16.h>
#include <cstdint>

#define NROWS  8192
#define HALF_N 4096
#define D      256
#define MT     128
#define NTILES 2080           // 64*65/2 upper-triangular block pairs
#define THREADS 256

// int8 panels: 128 rows x 256 B, XOR-swizzled. A @0, B @32768.
#define SM_A  0
#define SM_B  32768
#define SMEM_TOTAL 65536

__device__ uint8_t g_zq[NROWS * D];   // normalized rows, s8 (scale 127)
__device__ float g_part[NROWS];       // per-row exp-sum (diag excluded), atomic accum
__device__ float g_pos[NROWS];        // per-row positive-pair logit

// scale constants: dot_int = 127^2 * dot_real
#define INV_S2   (1.0f / 16129.0f)
#define EXP2_CS  (2.0f * 1.4426950408889634f * INV_S2)   // exp(2a) = exp2(acc*CS)
#define POS_CS   (2.0f * INV_S2)

// ---------------------------------------------------------------------------
__device__ __forceinline__ uint32_t smem_u32(const void* p) {
    uint32_t a;
    asm("{ .reg .u64 t; cvta.to.shared.u64 t, %1; cvt.u32.u64 %0, t; }" : "=r"(a) : "l"(p));
    return a;
}
__device__ __forceinline__ void cp16(uint32_t dst, const void* src) {
    asm volatile("cp.async.cg.shared.global [%0], [%1], 16;" :: "r"(dst), "l"(src) : "memory");
}
#define CP_COMMIT() asm volatile("cp.async.commit_group;" ::: "memory")
#define CP_WAIT(n)  asm volatile("cp.async.wait_group %0;" :: "n"(n) : "memory")

__device__ __forceinline__ void ldsm4(uint32_t* r, uint32_t addr) {
    asm volatile("ldmatrix.sync.aligned.m8n8.x4.shared.b16 {%0,%1,%2,%3}, [%4];"
        : "=r"(r[0]), "=r"(r[1]), "=r"(r[2]), "=r"(r[3]) : "r"(addr));
}
// s8 IMMA: D[16x8] += A[16x32] * B[32x8], s32 accumulate
__device__ __forceinline__ void mma_s8(int* c, const uint32_t* a,
                                       uint32_t b0, uint32_t b1) {
    asm volatile("mma.sync.aligned.m16n8k32.row.col.s32.s8.s8.s32 "
        "{%0,%1,%2,%3}, {%4,%5,%6,%7}, {%8,%9}, {%0,%1,%2,%3};"
        : "+r"(c[0]), "+r"(c[1]), "+r"(c[2]), "+r"(c[3])
        : "r"(a[0]), "r"(a[1]), "r"(a[2]), "r"(a[3]), "r"(b0), "r"(b1));
}
// pack 4 floats (|v|<=1) -> 4 s8 bytes scaled by 127 (little-endian x,y,z,w)
__device__ __forceinline__ uint32_t pack_s8x4(float x, float y, float z, float w) {
    int a = __float2int_rn(x * 127.f), b = __float2int_rn(y * 127.f);
    int c = __float2int_rn(z * 127.f), d = __float2int_rn(w * 127.f);
    uint32_t hi, r;
    asm("cvt.pack.sat.s8.s32.b32 %0, %1, %2, 0;" : "=r"(hi) : "r"(d), "r"(c));
    asm("cvt.pack.sat.s8.s32.b32 %0, %1, %2, %3;" : "=r"(r) : "r"(b), "r"(a), "r"(hi));
    return r;
}

// ---------------------------------------------------------------------------
// Kernel 1: L2-normalize rows -> s8 (2 rows per warp); zero accumulators.
// ---------------------------------------------------------------------------
__global__ void __launch_bounds__(256) norm_kernel(const float* __restrict__ z1,
                                                   const float* __restrict__ z2) {
    int tid = threadIdx.x;
    if (blockIdx.x < 32)                          // zero g_part (g_pos overwritten)
        g_part[blockIdx.x * 256 + tid] = 0.f;
    int wid = tid >> 5, lid = tid & 31;
    int row0 = blockIdx.x * 16 + wid * 2;
    int row1 = row0 + 1;
    const float* p0 = (row0 < HALF_N) ? z1 + (size_t)row0 * D
                                      : z2 + (size_t)(row0 - HALF_N) * D;
    const float* p1 = (row1 < HALF_N) ? z1 + (size_t)row1 * D
                                      : z2 + (size_t)(row1 - HALF_N) * D;
    const float4* s0 = (const float4*)p0;
    const float4* s1 = (const float4*)p1;
    float4 a0 = s0[lid], b0 = s0[lid + 32];
    float4 a1 = s1[lid], b1 = s1[lid + 32];
    float ss0 = a0.x*a0.x + a0.y*a0.y + a0.z*a0.z + a0.w*a0.w
              + b0.x*b0.x + b0.y*b0.y + b0.z*b0.z + b0.w*b0.w;
    float ss1 = a1.x*a1.x + a1.y*a1.y + a1.z*a1.z + a1.w*a1.w
              + b1.x*b1.x + b1.y*b1.y + b1.z*b1.z + b1.w*b1.w;
    #pragma unroll
    for (int o = 16; o > 0; o >>= 1) {
        ss0 += __shfl_xor_sync(0xffffffffu, ss0, o);
        ss1 += __shfl_xor_sync(0xffffffffu, ss1, o);
    }
    float inv0 = 1.0f / fmaxf(sqrtf(ss0), 1e-8f);
    float inv1 = 1.0f / fmaxf(sqrtf(ss1), 1e-8f);
    uint32_t* d0 = (uint32_t*)(g_zq + (size_t)row0 * D);
    uint32_t* d1 = (uint32_t*)(g_zq + (size_t)row1 * D);
    d0[lid]      = pack_s8x4(a0.x*inv0, a0.y*inv0, a0.z*inv0, a0.w*inv0);
    d0[lid + 32] = pack_s8x4(b0.x*inv0, b0.y*inv0, b0.z*inv0, b0.w*inv0);
    d1[lid]      = pack_s8x4(a1.x*inv1, a1.y*inv1, a1.z*inv1, a1.w*inv1);
    d1[lid + 32] = pack_s8x4(b1.x*inv1, b1.y*inv1, b1.z*inv1, b1.w*inv1);
}

// ---------------------------------------------------------------------------
// Kernel 2: symmetric s8 IMMA sim GEMM, K-split pipelined panel load.
// ---------------------------------------------------------------------------
__global__ void __launch_bounds__(THREADS, 2) sim_kernel() {
    __shared__ float rowsumArr[2][MT];           // sliced by cg
    __shared__ float colsumArr[4][MT];           // sliced by rgw
    extern __shared__ char smem[];
    uint32_t sb = smem_u32(smem);

    int tid = threadIdx.x, wid = tid >> 5, lane = tid & 31;
    int rgw = wid & 3;          // warp row-group: rows rgw*32 .. +31
    int cg  = wid >> 2;         // warp col-group: cols cg*64 .. +63

    // ---- map blockIdx -> (I, J), I <= J
    int t = blockIdx.x;
    int I = (int)(64.5f - sqrtf(64.5f * 64.5f - 2.0f * (float)t));
    if (I < 0) I = 0; if (I > 63) I = 63;
    while (I < 63 && (I + 1) * (128 - I) / 2 <= t) ++I;
    while (I > 0 && I * (129 - I) / 2 > t) --I;
    int J = I + (t - I * (129 - I) / 2);
    bool isDiag = (I == J), isPos = (J == I + 32);

    const char* gA = (const char*)(g_zq + (size_t)I * MT * D);
    const char* gB = (const char*)(g_zq + (size_t)J * MT * D);

    // ---- group 0: K-half 0 of both panels (chunks 0..7 per row)
    #pragma unroll
    for (int i = 0; i < 4; i++) {
        uint32_t c = i * 256 + tid, r = c >> 3, ch = c & 7;
        cp16(sb + SM_A + r * 256 + ((ch ^ (r & 7)) << 4),
             gA + (size_t)r * 256 + ch * 16);
    }
    #pragma unroll
    for (int i = 0; i < 4; i++) {
        uint32_t c = i * 256 + tid, r = c >> 3, ch = c & 7;
        cp16(sb + SM_B + r * 256 + ((ch ^ (r & 7)) << 4),
             gB + (size_t)r * 256 + ch * 16);
    }
    CP_COMMIT();
    // ---- group 1: K-half 1 (chunks 8..15)
    #pragma unroll
    for (int i = 0; i < 4; i++) {
        uint32_t c = i * 256 + tid, r = c >> 3, ch = (c & 7) + 8;
        cp16(sb + SM_A + r * 256 + ((ch ^ (r & 7)) << 4),
             gA + (size_t)r * 256 + ch * 16);
    }
    #pragma unroll
    for (int i = 0; i < 4; i++) {
        uint32_t c = i * 256 + tid, r = c >> 3, ch = (c & 7) + 8;
        cp16(sb + SM_B + r * 256 + ((ch ^ (r & 7)) << 4),
             gB + (size_t)r * 256 + ch * 16);
    }
    CP_COMMIT();

    #pragma unroll
    for (int s = 0; s < 2; s++) if (tid < MT) rowsumArr[s][tid] = 0.f;
    #pragma unroll
    for (int s = 0; s < 4; s++) if (tid < MT) colsumArr[s][tid] = 0.f;

    // ---- per-lane ldsm addressing (k32 fragment order, same as fp8)
    uint32_t mm = lane >> 3, rr = lane & 7;
    uint32_t rsel  = (mm & 1) * 8 + rr;
    uint32_t cbase = mm >> 1;
    uint32_t aRow0 = rgw * 32 + rsel, aRow1 = aRow0 + 16;
    uint32_t aBase0 = sb + SM_A + aRow0 * 256, aSwz0 = aRow0 & 7;
    uint32_t aBase1 = sb + SM_A + aRow1 * 256, aSwz1 = aRow1 & 7;
    uint32_t bRow[4], bSwz[4];
    #pragma unroll
    for (int q = 0; q < 4; q++) {
        uint32_t br = cg * 64 + q * 16 + rsel;
        bRow[q] = br * 256; bSwz[q] = br & 7;
    }

    int acc[2][8][4];
    #pragma unroll
    for (int rg = 0; rg < 2; rg++)
        #pragma unroll
        for (int nb = 0; nb < 8; nb++)
            #pragma unroll
            for (int e = 0; e < 4; e++) acc[rg][nb][e] = 0;

    // ---- K-half 0 compute (group 1 still streaming)
    CP_WAIT(1);
    __syncthreads();
    #pragma unroll
    for (int k = 0; k < 4; k++) {
        uint32_t ch = 2 * k + cbase;
        uint32_t a0[4], a1[4], b[4][4];
        ldsm4(a0, aBase0 + ((ch ^ aSwz0) << 4));
        ldsm4(a1, aBase1 + ((ch ^ aSwz1) << 4));
        #pragma unroll
        for (int q = 0; q < 4; q++)
            ldsm4(b[q], bRow[q] + sb + SM_B + ((ch ^ bSwz[q]) << 4));
        #pragma unroll
        for (int q = 0; q < 4; q++) {
            mma_s8(acc[0][2*q],   a0, b[q][0], b[q][2]);
            mma_s8(acc[0][2*q+1], a0, b[q][1], b[q][3]);
            mma_s8(acc[1][2*q],   a1, b[q][0], b[q][2]);
            mma_s8(acc[1][2*q+1], a1, b[q][1], b[q][3]);
        }
    }
    // ---- K-half 1 compute
    CP_WAIT(0);
    __syncthreads();
    #pragma unroll
    for (int k = 4; k < 8; k++) {
        uint32_t ch = 2 * k + cbase;
        uint32_t a0[4], a1[4], b[4][4];
        ldsm4(a0, aBase0 + ((ch ^ aSwz0) << 4));
        ldsm4(a1, aBase1 + ((ch ^ aSwz1) << 4));
        #pragma unroll
        for (int q = 0; q < 4; q++)
            ldsm4(b[q], bRow[q] + sb + SM_B + ((ch ^ bSwz[q]) << 4));
        #pragma unroll
        for (int q = 0; q < 4; q++) {
            mma_s8(acc[0][2*q],   a0, b[q][0], b[q][2]);
            mma_s8(acc[0][2*q+1], a0, b[q][1], b[q][3]);
            mma_s8(acc[1][2*q],   a1, b[q][0], b[q][2]);
            mma_s8(acc[1][2*q+1], a1, b[q][1], b[q][3]);
        }
    }

    // ---- epilogue: exp(2*dot) = exp2(acc * EXP2_CS)
    int ilBase = rgw * 32 + (lane >> 2);
    int jlBase = cg * 64 + ((lane & 3) << 1);
    float rsum[2][2] = {{0.f,0.f},{0.f,0.f}};
    float colacc[8][2];
    #pragma unroll
    for (int nb = 0; nb < 8; nb++) { colacc[nb][0] = 0.f; colacc[nb][1] = 0.f; }

    if (!isDiag && !isPos) {
        #pragma unroll
        for (int rg = 0; rg < 2; rg++)
            #pragma unroll
            for (int nb = 0; nb < 8; nb++)
                #pragma unroll
                for (int e = 0; e < 4; e++) {
                    float v = exp2f(EXP2_CS * (float)acc[rg][nb][e]);
                    rsum[rg][e >> 1] += v;
                    colacc[nb][e & 1] += v;
                }
    } else {
        #pragma unroll
        for (int rg = 0; rg < 2; rg++)
            #pragma unroll
            for (int e = 0; e < 4; e++) {
                int il = ilBase + rg * 16 + 8 * (e >> 1);
                #pragma unroll
                for (int nb = 0; nb < 8; nb++) {
                    int jl = jlBase + nb * 8 + (e & 1);
                    float v = exp2f(EXP2_CS * (float)acc[rg][nb][e]);
                    if (isDiag && jl == il) v = 0.f;        // exact self-skip
                    if (isPos && jl == il) {                // positive pair
                        float sim = POS_CS * (float)acc[rg][nb][e];
                        int gi = I * MT + il;
                        g_pos[gi] = sim; g_pos[gi + HALF_N] = sim;
                    }
                    rsum[rg][e >> 1] += v;
                    colacc[nb][e & 1] += v;
                }
            }
    }

    // row reduction: 4 lanes share a row; write to cg-slice (no atomics)
    #pragma unroll
    for (int rg = 0; rg < 2; rg++)
        #pragma unroll
        for (int h = 0; h < 2; h++) {
            float v = rsum[rg][h];
            v += __shfl_xor_sync(0xffffffffu, v, 1);
            v += __shfl_xor_sync(0xffffffffu, v, 2);
            if ((lane & 3) == 0)
                rowsumArr[cg][ilBase + rg * 16 + 8 * h] = v;
        }
    // column reduction: sum the 8 row-lanes; write to rgw-slice (no atomics)
    #pragma unroll
    for (int nb = 0; nb < 8; nb++)
        #pragma unroll
        for (int p = 0; p < 2; p++) {
            float v = colacc[nb][p];
            v += __shfl_xor_sync(0xffffffffu, v, 4);
            v += __shfl_xor_sync(0xffffffffu, v, 8);
            v += __shfl_xor_sync(0xffffffffu, v, 16);
            if (lane < 4)
                colsumArr[rgw][jlBase + nb * 8 + p] = v;
        }
    __syncthreads();

    if (tid < MT) {
        atomicAdd(&g_part[I * MT + tid], rowsumArr[0][tid] + rowsumArr[1][tid]);
    } else if (!isDiag) {
        int r = tid - MT;
        atomicAdd(&g_part[J * MT + r],
                  (colsumArr[0][r] + colsumArr[1][r]) +
                  (colsumArr[2][r] + colsumArr[3][r]));
    }
}

// ---------------------------------------------------------------------------
// Kernel 3: single-block fused per-row loss + mean.
// ---------------------------------------------------------------------------
__global__ void __launch_bounds__(1024) reduce_kernel(float* __restrict__ out) {
    __shared__ float red[1024];
    int t = threadIdx.x;
    float s = 0.0f;
    #pragma unroll
    for (int i = 0; i < 8; i++) {
        int r = t + i * 1024;
        s += logf(g_part[r]) - g_pos[r];
    }
    red[t] = s;
    __syncthreads();
    #pragma unroll
    for (int k = 512; k > 0; k >>= 1) {
        if (t < k) red[t] += red[t + k];
        __syncthreads();
    }
    if (t == 0) out[0] = red[0] / (float)NROWS;
}

// ---------------------------------------------------------------------------
extern "C" void kernel_launch(void* const* d_in, const int* in_sizes, int n_in,
                              void* d_out, int out_size) {
    const float* z1 = (const float*)d_in[0];
    const float* z2 = (const float*)d_in[1];
    float* out = (float*)d_out;

    cudaFuncSetAttribute(sim_kernel,
                         cudaFuncAttributeMaxDynamicSharedMemorySize, SMEM_TOTAL);

    norm_kernel<<<NROWS / 16, 256>>>(z1, z2);
    sim_kernel<<<NTILES, THREADS, SMEM_TOTAL>>>();
    reduce_kernel<<<1, 1024>>>(out);
}

// round 14
// speedup vs baseline: 1.8843x; 1.8843x over previous
#include <cuda_runtime.h>
#include <cuda_bf16.h>
#include <cstdint>

#define NROWS  8192
#define HALF_N 4096
#define D      256
#define MT     128
#define NTILES 2080           // 64*65/2 upper-triangular block pairs
#define THREADS 512

// fp8 panels: 128 rows x 256 B, XOR-swizzled. A @0, B @32768.
#define SM_A  0
#define SM_B  32768
#define SMEM_TOTAL 65536

__device__ uint8_t g_zq[NROWS * D];   // normalized rows, e4m3 (2 MB, L2-resident)
__device__ float g_part[NROWS];       // per-row exp-sum (diag excluded), atomic accum
__device__ float g_pos[NROWS];        // per-row positive-pair logit

// ---------------------------------------------------------------------------
__device__ __forceinline__ uint32_t smem_u32(const void* p) {
    uint32_t a;
    asm("{ .reg .u64 t; cvta.to.shared.u64 t, %1; cvt.u32.u64 %0, t; }" : "=r"(a) : "l"(p));
    return a;
}
__device__ __forceinline__ void cp16(uint32_t dst, const void* src) {
    asm volatile("cp.async.cg.shared.global [%0], [%1], 16;" :: "r"(dst), "l"(src) : "memory");
}
#define CP_COMMIT() asm volatile("cp.async.commit_group;" ::: "memory")
#define CP_WAIT(n)  asm volatile("cp.async.wait_group %0;" :: "n"(n) : "memory")

__device__ __forceinline__ void ldsm4(uint32_t* r, uint32_t addr) {
    asm volatile("ldmatrix.sync.aligned.m8n8.x4.shared.b16 {%0,%1,%2,%3}, [%4];"
        : "=r"(r[0]), "=r"(r[1]), "=r"(r[2]), "=r"(r[3]) : "r"(addr));
}
__device__ __forceinline__ void mma_fp8(float* c, const uint32_t* a,
                                        uint32_t b0, uint32_t b1) {
    asm volatile("mma.sync.aligned.m16n8k32.row.col.f32.e4m3.e4m3.f32 "
        "{%0,%1,%2,%3}, {%4,%5,%6,%7}, {%8,%9}, {%0,%1,%2,%3};"
        : "+f"(c[0]), "+f"(c[1]), "+f"(c[2]), "+f"(c[3])
        : "r"(a[0]), "r"(a[1]), "r"(a[2]), "r"(a[3]), "r"(b0), "r"(b1));
}
__device__ __forceinline__ uint32_t pack_e4m3x4(float x, float y, float z, float w) {
    uint16_t lo, hi;
    asm("cvt.rn.satfinite.e4m3x2.f32 %0, %1, %2;" : "=h"(lo) : "f"(y), "f"(x));
    asm("cvt.rn.satfinite.e4m3x2.f32 %0, %1, %2;" : "=h"(hi) : "f"(w), "f"(z));
    return (uint32_t)lo | ((uint32_t)hi << 16);
}

// ---------------------------------------------------------------------------
// Kernel 1: L2-normalize rows -> e4m3 (2 rows per warp); zero accumulators.
// ---------------------------------------------------------------------------
__global__ void __launch_bounds__(256) norm_kernel(const float* __restrict__ z1,
                                                   const float* __restrict__ z2) {
    int tid = threadIdx.x;
    if (blockIdx.x < 32)                          // zero g_part (g_pos overwritten)
        g_part[blockIdx.x * 256 + tid] = 0.f;
    int wid = tid >> 5, lid = tid & 31;
    int row0 = blockIdx.x * 16 + wid * 2;
    int row1 = row0 + 1;
    const float* p0 = (row0 < HALF_N) ? z1 + (size_t)row0 * D
                                      : z2 + (size_t)(row0 - HALF_N) * D;
    const float* p1 = (row1 < HALF_N) ? z1 + (size_t)row1 * D
                                      : z2 + (size_t)(row1 - HALF_N) * D;
    const float4* s0 = (const float4*)p0;
    const float4* s1 = (const float4*)p1;
    float4 a0 = s0[lid], b0 = s0[lid + 32];
    float4 a1 = s1[lid], b1 = s1[lid + 32];
    float ss0 = a0.x*a0.x + a0.y*a0.y + a0.z*a0.z + a0.w*a0.w
              + b0.x*b0.x + b0.y*b0.y + b0.z*b0.z + b0.w*b0.w;
    float ss1 = a1.x*a1.x + a1.y*a1.y + a1.z*a1.z + a1.w*a1.w
              + b1.x*b1.x + b1.y*b1.y + b1.z*b1.z + b1.w*b1.w;
    #pragma unroll
    for (int o = 16; o > 0; o >>= 1) {
        ss0 += __shfl_xor_sync(0xffffffffu, ss0, o);
        ss1 += __shfl_xor_sync(0xffffffffu, ss1, o);
    }
    float inv0 = 1.0f / fmaxf(sqrtf(ss0), 1e-8f);
    float inv1 = 1.0f / fmaxf(sqrtf(ss1), 1e-8f);
    uint32_t* d0 = (uint32_t*)(g_zq + (size_t)row0 * D);
    uint32_t* d1 = (uint32_t*)(g_zq + (size_t)row1 * D);
    d0[lid]      = pack_e4m3x4(a0.x*inv0, a0.y*inv0, a0.z*inv0, a0.w*inv0);
    d0[lid + 32] = pack_e4m3x4(b0.x*inv0, b0.y*inv0, b0.z*inv0, b0.w*inv0);
    d1[lid]      = pack_e4m3x4(a1.x*inv1, a1.y*inv1, a1.z*inv1, a1.w*inv1);
    d1[lid + 32] = pack_e4m3x4(b1.x*inv1, b1.y*inv1, b1.z*inv1, b1.w*inv1);
}

// ---------------------------------------------------------------------------
// Kernel 2: symmetric fp8 sim GEMM, 512 threads, warp tile m16 x n64.
// 16 warps = 8 row-groups x 2 col-groups; 2 CTAs/SM -> 32 warps/SM.
// ---------------------------------------------------------------------------
__global__ void __launch_bounds__(THREADS, 2) sim_kernel() {
    __shared__ float rowsumArr[2][MT];           // sliced by cg
    __shared__ float colsumArr[8][MT];           // sliced by rgw
    extern __shared__ char smem[];
    uint32_t sb = smem_u32(smem);

    int tid = threadIdx.x, wid = tid >> 5, lane = tid & 31;
    int rgw = wid & 7;          // warp row-group: rows rgw*16 .. +15
    int cg  = wid >> 3;         // warp col-group: cols cg*64 .. +63

    // ---- map blockIdx -> (I, J), I <= J
    int t = blockIdx.x;
    int I = (int)(64.5f - sqrtf(64.5f * 64.5f - 2.0f * (float)t));
    if (I < 0) I = 0; if (I > 63) I = 63;
    while (I < 63 && (I + 1) * (128 - I) / 2 <= t) ++I;
    while (I > 0 && I * (129 - I) / 2 > t) --I;
    int J = I + (t - I * (129 - I) / 2);
    bool isDiag = (I == J), isPos = (J == I + 32);

    const char* gA = (const char*)(g_zq + (size_t)I * MT * D);
    const char* gB = (const char*)(g_zq + (size_t)J * MT * D);

    // ---- group 0: K-half 0 of both panels (chunks 0..7 per row)
    #pragma unroll
    for (int i = 0; i < 2; i++) {
        uint32_t c = i * 512 + tid, r = c >> 3, ch = c & 7;
        cp16(sb + SM_A + r * 256 + ((ch ^ (r & 7)) << 4),
             gA + (size_t)r * 256 + ch * 16);
    }
    #pragma unroll
    for (int i = 0; i < 2; i++) {
        uint32_t c = i * 512 + tid, r = c >> 3, ch = c & 7;
        cp16(sb + SM_B + r * 256 + ((ch ^ (r & 7)) << 4),
             gB + (size_t)r * 256 + ch * 16);
    }
    CP_COMMIT();
    // ---- group 1: K-half 1 (chunks 8..15)
    #pragma unroll
    for (int i = 0; i < 2; i++) {
        uint32_t c = i * 512 + tid, r = c >> 3, ch = (c & 7) + 8;
        cp16(sb + SM_A + r * 256 + ((ch ^ (r & 7)) << 4),
             gA + (size_t)r * 256 + ch * 16);
    }
    #pragma unroll
    for (int i = 0; i < 2; i++) {
        uint32_t c = i * 512 + tid, r = c >> 3, ch = (c & 7) + 8;
        cp16(sb + SM_B + r * 256 + ((ch ^ (r & 7)) << 4),
             gB + (size_t)r * 256 + ch * 16);
    }
    CP_COMMIT();

    if (tid < MT) {
        rowsumArr[0][tid] = 0.f; rowsumArr[1][tid] = 0.f;
        #pragma unroll
        for (int s = 0; s < 8; s++) colsumArr[s][tid] = 0.f;
    }

    // ---- per-lane ldsm addressing (fp8 m16n8k32 fragment order)
    uint32_t mm = lane >> 3, rr = lane & 7;
    uint32_t rsel  = (mm & 1) * 8 + rr;
    uint32_t cbase = mm >> 1;
    uint32_t aRow  = rgw * 16 + rsel;
    uint32_t aBase = sb + SM_A + aRow * 256;
    uint32_t aSwz  = aRow & 7;
    uint32_t bRow[4], bSwz[4];
    #pragma unroll
    for (int q = 0; q < 4; q++) {
        uint32_t br = cg * 64 + q * 16 + rsel;
        bRow[q] = sb + SM_B + br * 256; bSwz[q] = br & 7;
    }

    float acc[8][4];
    #pragma unroll
    for (int nb = 0; nb < 8; nb++)
        #pragma unroll
        for (int e = 0; e < 4; e++) acc[nb][e] = 0.f;

    // ---- K-half 0 compute (group 1 still streaming)
    CP_WAIT(1);
    __syncthreads();
    #pragma unroll
    for (int k = 0; k < 4; k++) {
        uint32_t ch = 2 * k + cbase;
        uint32_t a[4];
        ldsm4(a, aBase + ((ch ^ aSwz) << 4));
        #pragma unroll
        for (int q = 0; q < 4; q++) {
            uint32_t b[4];
            ldsm4(b, bRow[q] + ((ch ^ bSwz[q]) << 4));
            mma_fp8(acc[2*q],   a, b[0], b[2]);
            mma_fp8(acc[2*q+1], a, b[1], b[3]);
        }
    }
    // ---- K-half 1 compute
    CP_WAIT(0);
    __syncthreads();
    #pragma unroll
    for (int k = 4; k < 8; k++) {
        uint32_t ch = 2 * k + cbase;
        uint32_t a[4];
        ldsm4(a, aBase + ((ch ^ aSwz) << 4));
        #pragma unroll
        for (int q = 0; q < 4; q++) {
            uint32_t b[4];
            ldsm4(b, bRow[q] + ((ch ^ bSwz[q]) << 4));
            mma_fp8(acc[2*q],   a, b[0], b[2]);
            mma_fp8(acc[2*q+1], a, b[1], b[3]);
        }
    }

    // ---- epilogue: exp(2a) = exp2(a * 2/ln2)
    const float C2 = 2.8853901817779268f;
    int ilBase = rgw * 16 + (lane >> 2);         // + 8*(e>>1)
    int jlBase = cg * 64 + ((lane & 3) << 1);    // + nb*8 + (e&1)
    float rsum[2] = {0.f, 0.f};
    float colacc[8][2];
    #pragma unroll
    for (int nb = 0; nb < 8; nb++) { colacc[nb][0] = 0.f; colacc[nb][1] = 0.f; }

    if (!isDiag && !isPos) {
        #pragma unroll
        for (int nb = 0; nb < 8; nb++)
            #pragma unroll
            for (int e = 0; e < 4; e++) {
                float v = exp2f(C2 * acc[nb][e]);
                rsum[e >> 1] += v;
                colacc[nb][e & 1] += v;
            }
    } else {
        #pragma unroll
        for (int e = 0; e < 4; e++) {
            int il = ilBase + 8 * (e >> 1);
            #pragma unroll
            for (int nb = 0; nb < 8; nb++) {
                int jl = jlBase + nb * 8 + (e & 1);
                float v = exp2f(C2 * acc[nb][e]);
                if (isDiag && jl == il) v = 0.f;            // exact self-skip
                if (isPos && jl == il) {                    // positive pair
                    float sim = 2.f * acc[nb][e];
                    int gi = I * MT + il;
                    g_pos[gi] = sim; g_pos[gi + HALF_N] = sim;
                }
                rsum[e >> 1] += v;
                colacc[nb][e & 1] += v;
            }
        }
    }

    // row reduction: 4 lanes share a row; write to cg-slice (no atomics)
    #pragma unroll
    for (int h = 0; h < 2; h++) {
        float v = rsum[h];
        v += __shfl_xor_sync(0xffffffffu, v, 1);
        v += __shfl_xor_sync(0xffffffffu, v, 2);
        if ((lane & 3) == 0)
            rowsumArr[cg][ilBase + 8 * h] = v;
    }
    // column reduction: sum the 8 row-lanes; write to rgw-slice (no atomics)
    #pragma unroll
    for (int nb = 0; nb < 8; nb++)
        #pragma unroll
        for (int p = 0; p < 2; p++) {
            float v = colacc[nb][p];
            v += __shfl_xor_sync(0xffffffffu, v, 4);
            v += __shfl_xor_sync(0xffffffffu, v, 8);
            v += __shfl_xor_sync(0xffffffffu, v, 16);
            if (lane < 4)
                colsumArr[rgw][jlBase + nb * 8 + p] = v;
        }
    __syncthreads();

    if (tid < MT) {
        atomicAdd(&g_part[I * MT + tid], rowsumArr[0][tid] + rowsumArr[1][tid]);
    } else if (tid < 2 * MT && !isDiag) {
        int r = tid - MT;
        float s = ((colsumArr[0][r] + colsumArr[1][r]) +
                   (colsumArr[2][r] + colsumArr[3][r])) +
                  ((colsumArr[4][r] + colsumArr[5][r]) +
                   (colsumArr[6][r] + colsumArr[7][r]));
        atomicAdd(&g_part[J * MT + r], s);
    }
}

// ---------------------------------------------------------------------------
// Kernel 3: single-block fused per-row loss + mean.
// ---------------------------------------------------------------------------
__global__ void __launch_bounds__(1024) reduce_kernel(float* __restrict__ out) {
    __shared__ float red[1024];
    int t = threadIdx.x;
    float s = 0.0f;
    #pragma unroll
    for (int i = 0; i < 8; i++) {
        int r = t + i * 1024;
        s += __logf(g_part[r]) - g_pos[r];
    }
    red[t] = s;
    __syncthreads();
    #pragma unroll
    for (int k = 512; k > 0; k >>= 1) {
        if (t < k) red[t] += red[t + k];
        __syncthreads();
    }
    if (t == 0) out[0] = red[0] / (float)NROWS;
}

// ---------------------------------------------------------------------------
extern "C" void kernel_launch(void* const* d_in, const int* in_sizes, int n_in,
                              void* d_out, int out_size) {
    const float* z1 = (const float*)d_in[0];
    const float* z2 = (const float*)d_in[1];
    float* out = (float*)d_out;

    cudaFuncSetAttribute(sim_kernel,
                         cudaFuncAttributeMaxDynamicSharedMemorySize, SMEM_TOTAL);

    norm_kernel<<<NROWS / 16, 256>>>(z1, z2);
    sim_kernel<<<NTILES, THREADS, SMEM_TOTAL>>>();
    reduce_kernel<<<1, 1024>>>(out);
}

// round 15
// speedup vs baseline: 2.1886x; 1.1615x over previous
#include <cuda_runtime.h>
#include <cuda_bf16.h>
#include <cstdint>

#define NROWS  8192
#define HALF_N 4096
#define D      256
#define MT     128
#define NTILES 2080           // 64*65/2 upper-triangular block pairs
#define THREADS 256

// fp8 panels: 128 rows x 256 B, XOR-swizzled. A @0, B @32768.
#define SM_A  0
#define SM_B  32768
#define SMEM_TOTAL 65536

__device__ uint8_t g_zq[NROWS * D];   // normalized rows, e4m3 (2 MB, L2-resident)
__device__ float g_part[NROWS];       // per-row exp-sum (diag excluded), atomic accum
__device__ float g_pos[NROWS];        // per-row positive-pair logit

// ---------------------------------------------------------------------------
__device__ __forceinline__ uint32_t smem_u32(const void* p) {
    uint32_t a;
    asm("{ .reg .u64 t; cvta.to.shared.u64 t, %1; cvt.u32.u64 %0, t; }" : "=r"(a) : "l"(p));
    return a;
}
__device__ __forceinline__ void cp16(uint32_t dst, const void* src) {
    asm volatile("cp.async.cg.shared.global [%0], [%1], 16;" :: "r"(dst), "l"(src) : "memory");
}
#define CP_COMMIT() asm volatile("cp.async.commit_group;" ::: "memory")
#define CP_WAIT(n)  asm volatile("cp.async.wait_group %0;" :: "n"(n) : "memory")

__device__ __forceinline__ void ldsm4(uint32_t* r, uint32_t addr) {
    asm volatile("ldmatrix.sync.aligned.m8n8.x4.shared.b16 {%0,%1,%2,%3}, [%4];"
        : "=r"(r[0]), "=r"(r[1]), "=r"(r[2]), "=r"(r[3]) : "r"(addr));
}
__device__ __forceinline__ void mma_fp8(float* c, const uint32_t* a,
                                        uint32_t b0, uint32_t b1) {
    asm volatile("mma.sync.aligned.m16n8k32.row.col.f32.e4m3.e4m3.f32 "
        "{%0,%1,%2,%3}, {%4,%5,%6,%7}, {%8,%9}, {%0,%1,%2,%3};"
        : "+f"(c[0]), "+f"(c[1]), "+f"(c[2]), "+f"(c[3])
        : "r"(a[0]), "r"(a[1]), "r"(a[2]), "r"(a[3]), "r"(b0), "r"(b1));
}
__device__ __forceinline__ uint32_t pack_e4m3x4(float x, float y, float z, float w) {
    uint16_t lo, hi;
    asm("cvt.rn.satfinite.e4m3x2.f32 %0, %1, %2;" : "=h"(lo) : "f"(y), "f"(x));
    asm("cvt.rn.satfinite.e4m3x2.f32 %0, %1, %2;" : "=h"(hi) : "f"(w), "f"(z));
    return (uint32_t)lo | ((uint32_t)hi << 16);
}

// ---------------------------------------------------------------------------
// Kernel 1: L2-normalize rows -> e4m3. 128 CTAs x 1024 threads (one wave),
// 2 rows per warp. Also zeroes g_part and out[0].
// ---------------------------------------------------------------------------
__global__ void __launch_bounds__(1024) norm_kernel(const float* __restrict__ z1,
                                                    const float* __restrict__ z2,
                                                    float* __restrict__ out) {
    int tid = threadIdx.x;
    if (blockIdx.x < 8)                           // zero g_part (g_pos overwritten)
        g_part[blockIdx.x * 1024 + tid] = 0.f;
    if (blockIdx.x == 8 && tid == 0) out[0] = 0.f;
    int wid = tid >> 5, lid = tid & 31;
    int row0 = blockIdx.x * 64 + wid * 2;
    int row1 = row0 + 1;
    const float* p0 = (row0 < HALF_N) ? z1 + (size_t)row0 * D
                                      : z2 + (size_t)(row0 - HALF_N) * D;
    const float* p1 = (row1 < HALF_N) ? z1 + (size_t)row1 * D
                                      : z2 + (size_t)(row1 - HALF_N) * D;
    const float4* s0 = (const float4*)p0;
    const float4* s1 = (const float4*)p1;
    float4 a0 = s0[lid], b0 = s0[lid + 32];
    float4 a1 = s1[lid], b1 = s1[lid + 32];
    float ss0 = a0.x*a0.x + a0.y*a0.y + a0.z*a0.z + a0.w*a0.w
              + b0.x*b0.x + b0.y*b0.y + b0.z*b0.z + b0.w*b0.w;
    float ss1 = a1.x*a1.x + a1.y*a1.y + a1.z*a1.z + a1.w*a1.w
              + b1.x*b1.x + b1.y*b1.y + b1.z*b1.z + b1.w*b1.w;
    #pragma unroll
    for (int o = 16; o > 0; o >>= 1) {
        ss0 += __shfl_xor_sync(0xffffffffu, ss0, o);
        ss1 += __shfl_xor_sync(0xffffffffu, ss1, o);
    }
    float inv0 = 1.0f / fmaxf(sqrtf(ss0), 1e-8f);
    float inv1 = 1.0f / fmaxf(sqrtf(ss1), 1e-8f);
    uint32_t* d0 = (uint32_t*)(g_zq + (size_t)row0 * D);
    uint32_t* d1 = (uint32_t*)(g_zq + (size_t)row1 * D);
    d0[lid]      = pack_e4m3x4(a0.x*inv0, a0.y*inv0, a0.z*inv0, a0.w*inv0);
    d0[lid + 32] = pack_e4m3x4(b0.x*inv0, b0.y*inv0, b0.z*inv0, b0.w*inv0);
    d1[lid]      = pack_e4m3x4(a1.x*inv1, a1.y*inv1, a1.z*inv1, a1.w*inv1);
    d1[lid + 32] = pack_e4m3x4(b1.x*inv1, b1.y*inv1, b1.z*inv1, b1.w*inv1);
}

// ---------------------------------------------------------------------------
// Kernel 2: symmetric fp8 sim GEMM, K-split pipelined panel load.
// (Best-known config: 256 threads, warp tile m32 x n64, 2 CTAs/SM.)
// ---------------------------------------------------------------------------
__global__ void __launch_bounds__(THREADS, 2) sim_kernel() {
    __shared__ float rowsumArr[2][MT];           // sliced by cg
    __shared__ float colsumArr[4][MT];           // sliced by rgw
    extern __shared__ char smem[];
    uint32_t sb = smem_u32(smem);

    int tid = threadIdx.x, wid = tid >> 5, lane = tid & 31;
    int rgw = wid & 3;          // warp row-group: rows rgw*32 .. +31
    int cg  = wid >> 2;         // warp col-group: cols cg*64 .. +63

    // ---- map blockIdx -> (I, J), I <= J
    int t = blockIdx.x;
    int I = (int)(64.5f - sqrtf(64.5f * 64.5f - 2.0f * (float)t));
    if (I < 0) I = 0; if (I > 63) I = 63;
    while (I < 63 && (I + 1) * (128 - I) / 2 <= t) ++I;
    while (I > 0 && I * (129 - I) / 2 > t) --I;
    int J = I + (t - I * (129 - I) / 2);
    bool isDiag = (I == J), isPos = (J == I + 32);

    const char* gA = (const char*)(g_zq + (size_t)I * MT * D);
    const char* gB = (const char*)(g_zq + (size_t)J * MT * D);

    // ---- group 0: K-half 0 of both panels (chunks 0..7 per row)
    #pragma unroll
    for (int i = 0; i < 4; i++) {
        uint32_t c = i * 256 + tid, r = c >> 3, ch = c & 7;
        cp16(sb + SM_A + r * 256 + ((ch ^ (r & 7)) << 4),
             gA + (size_t)r * 256 + ch * 16);
    }
    #pragma unroll
    for (int i = 0; i < 4; i++) {
        uint32_t c = i * 256 + tid, r = c >> 3, ch = c & 7;
        cp16(sb + SM_B + r * 256 + ((ch ^ (r & 7)) << 4),
             gB + (size_t)r * 256 + ch * 16);
    }
    CP_COMMIT();
    // ---- group 1: K-half 1 (chunks 8..15)
    #pragma unroll
    for (int i = 0; i < 4; i++) {
        uint32_t c = i * 256 + tid, r = c >> 3, ch = (c & 7) + 8;
        cp16(sb + SM_A + r * 256 + ((ch ^ (r & 7)) << 4),
             gA + (size_t)r * 256 + ch * 16);
    }
    #pragma unroll
    for (int i = 0; i < 4; i++) {
        uint32_t c = i * 256 + tid, r = c >> 3, ch = (c & 7) + 8;
        cp16(sb + SM_B + r * 256 + ((ch ^ (r & 7)) << 4),
             gB + (size_t)r * 256 + ch * 16);
    }
    CP_COMMIT();

    #pragma unroll
    for (int s = 0; s < 2; s++) if (tid < MT) rowsumArr[s][tid] = 0.f;
    #pragma unroll
    for (int s = 0; s < 4; s++) if (tid < MT) colsumArr[s][tid] = 0.f;

    // ---- per-lane ldsm addressing (fp8 m16n8k32 fragment order)
    uint32_t mm = lane >> 3, rr = lane & 7;
    uint32_t rsel  = (mm & 1) * 8 + rr;
    uint32_t cbase = mm >> 1;
    uint32_t aRow0 = rgw * 32 + rsel, aRow1 = aRow0 + 16;
    uint32_t aBase0 = sb + SM_A + aRow0 * 256, aSwz0 = aRow0 & 7;
    uint32_t aBase1 = sb + SM_A + aRow1 * 256, aSwz1 = aRow1 & 7;
    uint32_t bRow[4], bSwz[4];
    #pragma unroll
    for (int q = 0; q < 4; q++) {
        uint32_t br = cg * 64 + q * 16 + rsel;
        bRow[q] = br * 256; bSwz[q] = br & 7;
    }

    float acc[2][8][4];
    #pragma unroll
    for (int rg = 0; rg < 2; rg++)
        #pragma unroll
        for (int nb = 0; nb < 8; nb++)
            #pragma unroll
            for (int e = 0; e < 4; e++) acc[rg][nb][e] = 0.f;

    // ---- K-half 0 compute (group 1 still streaming)
    CP_WAIT(1);
    __syncthreads();
    #pragma unroll
    for (int k = 0; k < 4; k++) {
        uint32_t ch = 2 * k + cbase;
        uint32_t a0[4], a1[4], b[4][4];
        ldsm4(a0, aBase0 + ((ch ^ aSwz0) << 4));
        ldsm4(a1, aBase1 + ((ch ^ aSwz1) << 4));
        #pragma unroll
        for (int q = 0; q < 4; q++)
            ldsm4(b[q], bRow[q] + sb + SM_B + ((ch ^ bSwz[q]) << 4));
        #pragma unroll
        for (int q = 0; q < 4; q++) {
            mma_fp8(acc[0][2*q],   a0, b[q][0], b[q][2]);
            mma_fp8(acc[0][2*q+1], a0, b[q][1], b[q][3]);
            mma_fp8(acc[1][2*q],   a1, b[q][0], b[q][2]);
            mma_fp8(acc[1][2*q+1], a1, b[q][1], b[q][3]);
        }
    }
    // ---- K-half 1 compute
    CP_WAIT(0);
    __syncthreads();
    #pragma unroll
    for (int k = 4; k < 8; k++) {
        uint32_t ch = 2 * k + cbase;
        uint32_t a0[4], a1[4], b[4][4];
        ldsm4(a0, aBase0 + ((ch ^ aSwz0) << 4));
        ldsm4(a1, aBase1 + ((ch ^ aSwz1) << 4));
        #pragma unroll
        for (int q = 0; q < 4; q++)
            ldsm4(b[q], bRow[q] + sb + SM_B + ((ch ^ bSwz[q]) << 4));
        #pragma unroll
        for (int q = 0; q < 4; q++) {
            mma_fp8(acc[0][2*q],   a0, b[q][0], b[q][2]);
            mma_fp8(acc[0][2*q+1], a0, b[q][1], b[q][3]);
            mma_fp8(acc[1][2*q],   a1, b[q][0], b[q][2]);
            mma_fp8(acc[1][2*q+1], a1, b[q][1], b[q][3]);
        }
    }

    // ---- epilogue: exp(2a) = exp2(a * 2/ln2)
    const float C2 = 2.8853901817779268f;
    int ilBase = rgw * 32 + (lane >> 2);
    int jlBase = cg * 64 + ((lane & 3) << 1);
    float rsum[2][2] = {{0.f,0.f},{0.f,0.f}};
    float colacc[8][2];
    #pragma unroll
    for (int nb = 0; nb < 8; nb++) { colacc[nb][0] = 0.f; colacc[nb][1] = 0.f; }

    if (!isDiag && !isPos) {
        #pragma unroll
        for (int rg = 0; rg < 2; rg++)
            #pragma unroll
            for (int nb = 0; nb < 8; nb++)
                #pragma unroll
                for (int e = 0; e < 4; e++) {
                    float v = exp2f(C2 * acc[rg][nb][e]);
                    rsum[rg][e >> 1] += v;
                    colacc[nb][e & 1] += v;
                }
    } else {
        #pragma unroll
        for (int rg = 0; rg < 2; rg++)
            #pragma unroll
            for (int e = 0; e < 4; e++) {
                int il = ilBase + rg * 16 + 8 * (e >> 1);
                #pragma unroll
                for (int nb = 0; nb < 8; nb++) {
                    int jl = jlBase + nb * 8 + (e & 1);
                    float v = exp2f(C2 * acc[rg][nb][e]);
                    if (isDiag && jl == il) v = 0.f;        // exact self-skip
                    if (isPos && jl == il) {                // positive pair
                        float sim = 2.f * acc[rg][nb][e];
                        int gi = I * MT + il;
                        g_pos[gi] = sim; g_pos[gi + HALF_N] = sim;
                    }
                    rsum[rg][e >> 1] += v;
                    colacc[nb][e & 1] += v;
                }
            }
    }

    // row reduction: 4 lanes share a row; write to cg-slice (no atomics)
    #pragma unroll
    for (int rg = 0; rg < 2; rg++)
        #pragma unroll
        for (int h = 0; h < 2; h++) {
            float v = rsum[rg][h];
            v += __shfl_xor_sync(0xffffffffu, v, 1);
            v += __shfl_xor_sync(0xffffffffu, v, 2);
            if ((lane & 3) == 0)
                rowsumArr[cg][ilBase + rg * 16 + 8 * h] = v;
        }
    // column reduction: sum the 8 row-lanes; write to rgw-slice (no atomics)
    #pragma unroll
    for (int nb = 0; nb < 8; nb++)
        #pragma unroll
        for (int p = 0; p < 2; p++) {
            float v = colacc[nb][p];
            v += __shfl_xor_sync(0xffffffffu, v, 4);
            v += __shfl_xor_sync(0xffffffffu, v, 8);
            v += __shfl_xor_sync(0xffffffffu, v, 16);
            if (lane < 4)
                colsumArr[rgw][jlBase + nb * 8 + p] = v;
        }
    __syncthreads();

    if (tid < MT) {
        atomicAdd(&g_part[I * MT + tid], rowsumArr[0][tid] + rowsumArr[1][tid]);
    } else if (!isDiag) {
        int r = tid - MT;
        atomicAdd(&g_part[J * MT + r],
                  (colsumArr[0][r] + colsumArr[1][r]) +
                  (colsumArr[2][r] + colsumArr[3][r]));
    }
}

// ---------------------------------------------------------------------------
// Kernel 3: multi-block per-row loss + atomic mean (out pre-zeroed by norm).
// ---------------------------------------------------------------------------
__global__ void __launch_bounds__(512) reduce_kernel(float* __restrict__ out) {
    __shared__ float red[512];
    int t = threadIdx.x;
    int r = blockIdx.x * 512 + t;
    red[t] = __logf(g_part[r]) - g_pos[r];
    __syncthreads();
    #pragma unroll
    for (int k = 256; k > 32; k >>= 1) {
        if (t < k) red[t] += red[t + k];
        __syncthreads();
    }
    if (t < 32) {
        float v = red[t] + red[t + 32];
        #pragma unroll
        for (int o = 16; o > 0; o >>= 1) v += __shfl_xor_sync(0xffffffffu, v, o);
        if (t == 0) atomicAdd(out, v * (1.0f / (float)NROWS));
    }
}

// ---------------------------------------------------------------------------
extern "C" void kernel_launch(void* const* d_in, const int* in_sizes, int n_in,
                              void* d_out, int out_size) {
    const float* z1 = (const float*)d_in[0];
    const float* z2 = (const float*)d_in[1];
    float* out = (float*)d_out;

    cudaFuncSetAttribute(sim_kernel,
                         cudaFuncAttributeMaxDynamicSharedMemorySize, SMEM_TOTAL);

    norm_kernel<<<NROWS / 64, 1024>>>(z1, z2, out);
    sim_kernel<<<NTILES, THREADS, SMEM_TOTAL>>>();
    reduce_kernel<<<NROWS / 512, 512>>>(out);
}